// round 1
// baseline (speedup 1.0000x reference)
#include <cuda_runtime.h>
#include <math.h>

#define GAMMA_F 0.99f
#define TAU 64   // tau == tauP == 64 for this problem

// Kernel 1: one CTA per batch element b, blockDim = TAU (64 threads).
// Thread t owns current-quantile index tau=t (qsa, rq in registers) and
// target-quantile index tp=t (computes target[t] into shared).
__global__ void __launch_bounds__(TAU)
iqn_td_kernel(const float* __restrict__ q,          // (tau, B, N)
              const float* __restrict__ next_n_q,   // (tauP, B, N)
              const int*   __restrict__ action,     // (B,)
              const int*   __restrict__ next_action,// (B,)
              const float* __restrict__ reward,     // (T, B)
              const int*   __restrict__ done,       // (B,)
              const float* __restrict__ replay_q,   // (tau, B)
              float* __restrict__ td_out,           // (B,)  == out+1
              int B, int N, int T, float gamma_T)
{
    const int b   = blockIdx.x;
    const int t   = threadIdx.x;

    __shared__ float s_target[TAU];
    __shared__ float s_red[2];

    const int a  = action[b];
    const int an = next_action[b];

    // strided gathers: one element per (t, b)
    const long long plane = (long long)B * (long long)N;
    const long long base  = (long long)t * plane + (long long)b * (long long)N;
    const float qsa  = q[base + a];
    const float tgtq = next_n_q[base + an];

    const float rq  = replay_q[t * B + b];
    const float rq1 = 1.0f - rq;

    // n-step discounted reward sum (uniform across block; cheap, T=3)
    float r_sum = 0.0f, g = 1.0f;
    #pragma unroll 4
    for (int tt = 0; tt < T; ++tt) {
        r_sum = fmaf(g, reward[tt * B + b], r_sum);
        g *= GAMMA_F;
    }
    const float nd = (done[b] != 0) ? 0.0f : 1.0f;

    // bellman target for this thread's tp index
    s_target[t] = fmaf(gamma_T * nd, tgtq, r_sum);
    __syncthreads();

    // pairwise quantile-huber accumulation:
    //   kappa = 1:  huber = 0.5*c*c + (|u| - c),  c = min(|u|, 1)
    //   factor = |rq - 1(u<0)| = (u<0) ? (1-rq) : rq
    float acc = 0.0f;
    #pragma unroll
    for (int tp = 0; tp < TAU; ++tp) {
        const float tgt = s_target[tp];      // broadcast LDS
        const float u   = tgt - qsa;
        const float au  = fabsf(u);
        const float c   = fminf(au, 1.0f);
        const float h   = fmaf(0.5f * c, c, au - c);
        const float f   = (u < 0.0f) ? rq1 : rq;
        acc = fmaf(f, h, acc);
    }

    // reduce 64 threads (2 warps)
    #pragma unroll
    for (int off = 16; off > 0; off >>= 1)
        acc += __shfl_down_sync(0xffffffffu, acc, off);
    if ((t & 31) == 0) s_red[t >> 5] = acc;
    __syncthreads();
    if (t == 0)
        td_out[b] = (s_red[0] + s_red[1]) * (1.0f / (float)TAU); // mean over tauP
}

// Kernel 2: deterministic weighted-mean reduction -> loss at out[0]
__global__ void __launch_bounds__(256)
iqn_loss_kernel(const float* __restrict__ td,
                const float* __restrict__ weight,
                float* __restrict__ out0,
                int B)
{
    __shared__ float s[256];
    float acc = 0.0f;
    for (int i = threadIdx.x; i < B; i += 256)
        acc = fmaf(td[i], weight[i], acc);
    s[threadIdx.x] = acc;
    __syncthreads();
    #pragma unroll
    for (int off = 128; off > 0; off >>= 1) {
        if (threadIdx.x < off) s[threadIdx.x] += s[threadIdx.x + off];
        __syncthreads();
    }
    if (threadIdx.x == 0) out0[0] = s[0] / (float)B;
}

extern "C" void kernel_launch(void* const* d_in, const int* in_sizes, int n_in,
                              void* d_out, int out_size)
{
    const float* q        = (const float*)d_in[0];
    const float* next_n_q = (const float*)d_in[1];
    const int*   action   = (const int*)  d_in[2];
    const int*   naction  = (const int*)  d_in[3];
    const float* reward   = (const float*)d_in[4];
    const int*   done     = (const int*)  d_in[5];
    const float* replay_q = (const float*)d_in[6];
    const float* weight   = (const float*)d_in[7];

    const int B    = in_sizes[2];                 // action count
    const int tau  = in_sizes[6] / B;             // replay_quantiles = (tau, B)
    const int N    = in_sizes[0] / (tau * B);     // q = (tau, B, N)
    const int T    = in_sizes[4] / B;             // reward = (T, B)

    float gamma_T = 1.0f;
    for (int i = 0; i < T; ++i) gamma_T *= GAMMA_F;

    float* out = (float*)d_out;   // out[0] = loss, out[1..B] = td_error_per_sample

    iqn_td_kernel<<<B, TAU>>>(q, next_n_q, action, naction, reward, done,
                              replay_q, out + 1, B, N, T, gamma_T);
    iqn_loss_kernel<<<1, 256>>>(out + 1, weight, out, B);
}